// round 4
// baseline (speedup 1.0000x reference)
#include <cuda_runtime.h>
#include <cuda_bf16.h>
#include <stdint.h>

#define BATCH 2048
#define HW81  81
#define CDIM  512
#define HID   256
#define MROWS (BATCH * HW81)   /* 165888 */

// Scratch: xq = x @ W^T + b, in x's natural row order [B*81, 256] fp32 (170 MB)
__device__ float g_Y[(size_t)MROWS * HID];

// ---------------------------------------------------------------------------
// helpers
// ---------------------------------------------------------------------------
__device__ __forceinline__ void bsplit(float v, __nv_bfloat16& h, __nv_bfloat16& l) {
    h = __float2bfloat16(v);
    l = __float2bfloat16(v - __bfloat162float(h));
}

__device__ __forceinline__ uint32_t pack2(__nv_bfloat16 a, __nv_bfloat16 b) {
    __nv_bfloat162 t;
    t.x = a; t.y = b;           // .x occupies low 16 bits in memory order
    uint32_t r;
    memcpy(&r, &t, 4);
    return r;
}

__device__ __forceinline__ void mma16816(float* c, const uint32_t* a, const uint32_t* b) {
    asm volatile(
        "mma.sync.aligned.m16n8k16.row.col.f32.bf16.bf16.f32 "
        "{%0,%1,%2,%3}, {%4,%5,%6,%7}, {%8,%9}, {%0,%1,%2,%3};\n"
        : "+f"(c[0]), "+f"(c[1]), "+f"(c[2]), "+f"(c[3])
        : "r"(a[0]), "r"(a[1]), "r"(a[2]), "r"(a[3]), "r"(b[0]), "r"(b[1]));
}

// ---------------------------------------------------------------------------
// Kernel 1: Y[r, n] = sum_k X[r,k] * W[n,k] + b[n]
// CTA tile 128(M) x 64(N), K staged 32 at a time, bf16 hi/lo 3-MMA split.
// grid = (HID/64 = 4, MROWS/128 = 1296)  -> adjacent CTAs share A rows (L2 reuse)
// ---------------------------------------------------------------------------
__global__ __launch_bounds__(256, 2)
void gemm_kernel(const float* __restrict__ X,
                 const float* __restrict__ Wf,
                 const float* __restrict__ bfc)
{
    // stride 40 (pad +8) => conflict-free for both the frag loads and stores
    __shared__ __align__(16) __nv_bfloat16 Ah[128][40];
    __shared__ __align__(16) __nv_bfloat16 Al[128][40];
    __shared__ __align__(16) __nv_bfloat16 Bh[64][40];
    __shared__ __align__(16) __nv_bfloat16 Bl[64][40];

    const int tid  = threadIdx.x;
    const int lane = tid & 31;
    const int warp = tid >> 5;
    const int wm   = warp >> 1;             // 0..3  (M direction)
    const int wn   = warp & 1;              // 0..1  (N direction)
    const int row0 = blockIdx.y * 128;
    const int col0 = blockIdx.x * 64;

    float acc[2][4][4];
#pragma unroll
    for (int a = 0; a < 2; a++)
#pragma unroll
        for (int b = 0; b < 4; b++)
#pragma unroll
            for (int d = 0; d < 4; d++) acc[a][b][d] = 0.f;

    const int lk4 = (tid & 7) << 2;         // k offset 0..28 step 4
    const int lr  = tid >> 3;               // 0..31

    for (int k0 = 0; k0 < CDIM; k0 += 32) {
        __syncthreads();
        // ---- load A tile 128x32 (fp32 -> bf16 hi/lo) ----
#pragma unroll
        for (int rr = 0; rr < 4; rr++) {
            int row = lr + rr * 32;
            float4 v = *(const float4*)(X + (size_t)(row0 + row) * CDIM + k0 + lk4);
            __nv_bfloat16 h0, h1, h2, h3, l0, l1, l2, l3;
            bsplit(v.x, h0, l0); bsplit(v.y, h1, l1);
            bsplit(v.z, h2, l2); bsplit(v.w, h3, l3);
            uint32_t* dh = (uint32_t*)&Ah[row][lk4];
            dh[0] = pack2(h0, h1); dh[1] = pack2(h2, h3);
            uint32_t* dl = (uint32_t*)&Al[row][lk4];
            dl[0] = pack2(l0, l1); dl[1] = pack2(l2, l3);
        }
        // ---- load B tile 64x32 from W[n][k] (already the col-major layout mma wants) ----
#pragma unroll
        for (int nn = 0; nn < 2; nn++) {
            int nr = lr + nn * 32;
            float4 v = *(const float4*)(Wf + (size_t)(col0 + nr) * CDIM + k0 + lk4);
            __nv_bfloat16 h0, h1, h2, h3, l0, l1, l2, l3;
            bsplit(v.x, h0, l0); bsplit(v.y, h1, l1);
            bsplit(v.z, h2, l2); bsplit(v.w, h3, l3);
            uint32_t* dh = (uint32_t*)&Bh[nr][lk4];
            dh[0] = pack2(h0, h1); dh[1] = pack2(h2, h3);
            uint32_t* dl = (uint32_t*)&Bl[nr][lk4];
            dl[0] = pack2(l0, l1); dl[1] = pack2(l2, l3);
        }
        __syncthreads();

#pragma unroll
        for (int kk = 0; kk < 32; kk += 16) {
            uint32_t ah[2][4], al[2][4], bh[4][2], bl[4][2];
#pragma unroll
            for (int mt = 0; mt < 2; mt++) {
                int r  = wm * 32 + mt * 16 + (lane >> 2);
                int cc = kk + ((lane & 3) << 1);
                ah[mt][0] = *(const uint32_t*)&Ah[r][cc];
                ah[mt][1] = *(const uint32_t*)&Ah[r + 8][cc];
                ah[mt][2] = *(const uint32_t*)&Ah[r][cc + 8];
                ah[mt][3] = *(const uint32_t*)&Ah[r + 8][cc + 8];
                al[mt][0] = *(const uint32_t*)&Al[r][cc];
                al[mt][1] = *(const uint32_t*)&Al[r + 8][cc];
                al[mt][2] = *(const uint32_t*)&Al[r][cc + 8];
                al[mt][3] = *(const uint32_t*)&Al[r + 8][cc + 8];
            }
#pragma unroll
            for (int nt = 0; nt < 4; nt++) {
                int cN = wn * 32 + nt * 8 + (lane >> 2);
                int ck = kk + ((lane & 3) << 1);
                bh[nt][0] = *(const uint32_t*)&Bh[cN][ck];
                bh[nt][1] = *(const uint32_t*)&Bh[cN][ck + 8];
                bl[nt][0] = *(const uint32_t*)&Bl[cN][ck];
                bl[nt][1] = *(const uint32_t*)&Bl[cN][ck + 8];
            }
#pragma unroll
            for (int mt = 0; mt < 2; mt++)
#pragma unroll
                for (int nt = 0; nt < 4; nt++) {
                    mma16816(acc[mt][nt], ah[mt], bh[nt]);   // hi*hi
                    mma16816(acc[mt][nt], al[mt], bh[nt]);   // lo*hi
                    mma16816(acc[mt][nt], ah[mt], bl[nt]);   // hi*lo
                }
        }
    }

    // epilogue: + bias, write fp32
#pragma unroll
    for (int mt = 0; mt < 2; mt++) {
        int r = row0 + wm * 32 + mt * 16 + (lane >> 2);
#pragma unroll
        for (int nt = 0; nt < 4; nt++) {
            int c  = col0 + wn * 32 + nt * 8 + ((lane & 3) << 1);
            float b0 = __ldg(bfc + c);
            float b1 = __ldg(bfc + c + 1);
            float2 v0 = make_float2(acc[mt][nt][0] + b0, acc[mt][nt][1] + b1);
            float2 v1 = make_float2(acc[mt][nt][2] + b0, acc[mt][nt][3] + b1);
            *(float2*)&g_Y[(size_t)r * HID + c]       = v0;
            *(float2*)&g_Y[(size_t)(r + 8) * HID + c] = v1;
        }
    }
}

// ---------------------------------------------------------------------------
// Kernel 2: per-batch attention. One CTA (256 threads) per batch.
//   attn[n,m] = (1/48) * sum_{p,h} xq[n,p,h] xq[m,p,h]   (- 100 on diag)
//   attn2     = softmax_k( (attn @ attn^T) / 3 )
//   P         = softmax_m( attn + attn2 )
//   out[n,p,c]= sum_m P[n,m] * x[m,p,c]
// rowmap(q,p) = (3*(q/3)+p/3)*9 + 3*(q%3)+(p%3)
// ---------------------------------------------------------------------------
__global__ __launch_bounds__(256)
void attn_kernel(const float* __restrict__ X, float* __restrict__ out)
{
    const int b    = blockIdx.x;
    const int tid  = threadIdx.x;
    const int lane = tid & 31;
    const int warp = tid >> 5;

    __shared__ float sRed[8][45];
    __shared__ float sAttn[81];
    __shared__ float sB[81];
    __shared__ float sP[81];

    const float* Yb = g_Y + (size_t)b * (HW81 * HID);

    // --- step 1: syrk — each xq element read exactly once ---
    float acc[45];
#pragma unroll
    for (int i = 0; i < 45; i++) acc[i] = 0.f;

#pragma unroll
    for (int p = 0; p < 9; p++) {
        float z[9];
#pragma unroll
        for (int q = 0; q < 9; q++) {
            int rm = (3 * (q / 3) + p / 3) * 9 + 3 * (q % 3) + (p % 3);
            z[q] = Yb[rm * HID + tid];
        }
        int cidx = 0;
#pragma unroll
        for (int n = 0; n < 9; n++)
#pragma unroll
            for (int m = n; m < 9; m++)
                acc[cidx++] += z[n] * z[m];
    }
#pragma unroll
    for (int i = 0; i < 45; i++) {
        float v = acc[i];
#pragma unroll
        for (int o = 16; o > 0; o >>= 1) v += __shfl_xor_sync(0xffffffffu, v, o);
        if (lane == 0) sRed[warp][i] = v;
    }
    __syncthreads();

    if (tid < 45) {
        float s = 0.f;
#pragma unroll
        for (int w = 0; w < 8; w++) s += sRed[w][tid];
        int n = 0, m = tid;
        while (m >= 9 - n) { m -= (9 - n); n++; }
        m += n;
        float v = s * (1.0f / 48.0f);     // (hidden*P)^-0.5 = 1/sqrt(2304)
        if (n == m) v -= 100.0f;          // diagonal self-suppression
        sAttn[n * 9 + m] = v;
        sAttn[m * 9 + n] = v;
    }
    __syncthreads();

    // --- step 2: attnB = attn @ attn^T / 3 ---
    if (tid < 81) {
        int n = tid / 9, k = tid % 9;
        float s = 0.f;
#pragma unroll
        for (int m = 0; m < 9; m++) s += sAttn[n * 9 + m] * sAttn[k * 9 + m];
        sB[tid] = s * (1.0f / 3.0f);
    }
    __syncthreads();

    // --- softmax chain, one thread per row (9 rows, trivial work) ---
    if (tid < 9) {
        int n = tid;
        float mx = -1e30f;
#pragma unroll
        for (int k = 0; k < 9; k++) mx = fmaxf(mx, sB[n * 9 + k]);
        float e[9]; float se = 0.f;
#pragma unroll
        for (int k = 0; k < 9; k++) { e[k] = expf(sB[n * 9 + k] - mx); se += e[k]; }
        float inv = 1.0f / se;
        float L[9]; float mx2 = -1e30f;
#pragma unroll
        for (int k = 0; k < 9; k++) {
            L[k] = sAttn[n * 9 + k] + e[k] * inv;
            mx2 = fmaxf(mx2, L[k]);
        }
        float e2[9]; float s2 = 0.f;
#pragma unroll
        for (int k = 0; k < 9; k++) { e2[k] = expf(L[k] - mx2); s2 += e2[k]; }
        float inv2 = 1.0f / s2;
#pragma unroll
        for (int k = 0; k < 9; k++) sP[n * 9 + k] = e2[k] * inv2;
    }
    __syncthreads();

    // --- step 3: out = P @ v ; each x element read once, each out written once ---
    const float2* Xb = (const float2*)X + (size_t)b * (HW81 * 256);
    float2*       Ob = (float2*)out     + (size_t)b * (HW81 * 256);

#pragma unroll
    for (int p = 0; p < 9; p++) {
        float2 v[9];
#pragma unroll
        for (int m = 0; m < 9; m++) {
            int rm = (3 * (m / 3) + p / 3) * 9 + 3 * (m % 3) + (p % 3);
            v[m] = Xb[rm * 256 + tid];
        }
#pragma unroll
        for (int n = 0; n < 9; n++) {
            int rm = (3 * (n / 3) + p / 3) * 9 + 3 * (n % 3) + (p % 3);
            float2 o = make_float2(0.f, 0.f);
#pragma unroll
            for (int m = 0; m < 9; m++) {
                float w = sP[n * 9 + m];
                o.x += w * v[m].x;
                o.y += w * v[m].y;
            }
            Ob[rm * 256 + tid] = o;
        }
    }
}

// ---------------------------------------------------------------------------
extern "C" void kernel_launch(void* const* d_in, const int* in_sizes, int n_in,
                              void* d_out, int out_size)
{
    const float* x   = (const float*)d_in[0];   // [2048, 9, 9, 512] fp32
    const float* Wf  = (const float*)d_in[1];   // [256, 512] fp32
    const float* bfc = (const float*)d_in[2];   // [256] fp32
    float* out = (float*)d_out;

    dim3 g1(HID / 64, MROWS / 128);             // (4, 1296)
    gemm_kernel<<<g1, 256>>>(x, Wf, bfc);
    attn_kernel<<<BATCH, 256>>>(x, out);
}

// round 6
// speedup vs baseline: 1.3165x; 1.3165x over previous
#include <cuda_runtime.h>
#include <cuda_bf16.h>
#include <stdint.h>

#define BATCH 2048
#define HW81  81
#define CDIM  512
#define HID   256
#define MROWS (BATCH * HW81)   /* 165888 */

// Scratch: xq = x @ W^T + b, [B*81, 256] fp32 (170 MB)
__device__ float g_Y[(size_t)MROWS * HID];
// W pre-rounded to tf32 format (stored as fp32 bit patterns), [256][512]
__device__ float g_Wt[HID * CDIM];

// ---------------------------------------------------------------------------
// helpers
// ---------------------------------------------------------------------------
__device__ __forceinline__ uint32_t f2tf32(float f) {
    uint32_t u;
    asm("cvt.rna.tf32.f32 %0, %1;" : "=r"(u) : "f"(f));
    return u;
}

__device__ __forceinline__ uint32_t smem_u32(const void* p) {
    uint32_t a;
    asm("{ .reg .u64 t; cvta.to.shared.u64 t, %1; cvt.u32.u64 %0, t; }" : "=r"(a) : "l"(p));
    return a;
}

__device__ __forceinline__ void cp16(uint32_t dst, const void* src) {
    asm volatile("cp.async.cg.shared.global [%0], [%1], 16;" :: "r"(dst), "l"(src));
}

__device__ __forceinline__ void mma_tf32(float* c, uint32_t a0, uint32_t a1,
                                         uint32_t a2, uint32_t a3,
                                         uint32_t b0, uint32_t b1) {
    asm volatile(
        "mma.sync.aligned.m16n8k8.row.col.f32.tf32.tf32.f32 "
        "{%0,%1,%2,%3}, {%4,%5,%6,%7}, {%8,%9}, {%0,%1,%2,%3};\n"
        : "+f"(c[0]), "+f"(c[1]), "+f"(c[2]), "+f"(c[3])
        : "r"(a0), "r"(a1), "r"(a2), "r"(a3), "r"(b0), "r"(b1));
}

// ---------------------------------------------------------------------------
// Kernel 0: round W to tf32 (RNA) once.
// ---------------------------------------------------------------------------
__global__ void wprep_kernel(const float* __restrict__ Wf) {
    int i = blockIdx.x * 512 + threadIdx.x;
    uint32_t u = f2tf32(Wf[i]);
    g_Wt[i] = __uint_as_float(u);
}

// ---------------------------------------------------------------------------
// Kernel 1: TF32 GEMM.  Y[r,n] = sum_k X[r,k]*W[n,k] + b[n]
// CTA tile 256(M) x 128(N), 512 threads = 16 warps (4M x 4N), warp tile 64x32.
// K staged 64 at a time, cp.async double-buffered.
// smem stride 68 floats -> all fragment LDS bank-conflict-free.
// grid = (HID/128 = 2, MROWS/256 = 648): adjacent CTAs share A rows (L2 reuse).
// ---------------------------------------------------------------------------
#define STRIDE   68
#define OFF_A0   0
#define OFF_A1   (256 * STRIDE)              /* 17408 */
#define OFF_B0   (2 * 256 * STRIDE)          /* 34816 */
#define OFF_B1   (OFF_B0 + 128 * STRIDE)     /* 43520 */
#define SMEM_FLOATS (OFF_B1 + 128 * STRIDE)  /* 52224 floats = 208896 B */

__global__ __launch_bounds__(512, 1)
void gemm_tf32(const float* __restrict__ X, const float* __restrict__ bfc)
{
    extern __shared__ __align__(16) float smem[];

    const int tid  = threadIdx.x;
    const int lane = tid & 31;
    const int warp = tid >> 5;
    const int wm   = warp >> 2;          // 0..3 (M)
    const int wn   = warp & 3;           // 0..3 (N)
    const int row0 = blockIdx.y * 256;
    const int col0 = blockIdx.x * 128;
    const uint32_t sbase = smem_u32(smem);

    float acc[4][4][4];
#pragma unroll
    for (int a = 0; a < 4; a++)
#pragma unroll
        for (int b = 0; b < 4; b++)
#pragma unroll
            for (int d = 0; d < 4; d++) acc[a][b][d] = 0.f;

    // ---- stage issuer (A: 8 x 16B per thread, B: 4 x 16B per thread) ----
    const float* Xc = X + (size_t)row0 * CDIM;
    const float* Wc = g_Wt + (size_t)col0 * CDIM;

#define ISSUE_STAGE(IT, OFFA, OFFB)                                          \
    do {                                                                     \
        const int k0 = (IT) * 64;                                            \
        _Pragma("unroll")                                                    \
        for (int i = 0; i < 8; i++) {                                        \
            int f = i * 512 + tid;  /* 0..4095 */                            \
            int r = f >> 4, j = (f & 15) << 2;                               \
            cp16(sbase + ((OFFA) + r * STRIDE + j) * 4,                      \
                 Xc + (size_t)r * CDIM + k0 + j);                            \
        }                                                                    \
        _Pragma("unroll")                                                    \
        for (int i = 0; i < 4; i++) {                                        \
            int f = i * 512 + tid;  /* 0..2047 */                            \
            int r = f >> 4, j = (f & 15) << 2;                               \
            cp16(sbase + ((OFFB) + r * STRIDE + j) * 4,                      \
                 Wc + (size_t)r * CDIM + k0 + j);                            \
        }                                                                    \
        asm volatile("cp.async.commit_group;" ::: "memory");                 \
    } while (0)

    ISSUE_STAGE(0, OFF_A0, OFF_B0);
    ISSUE_STAGE(1, OFF_A1, OFF_B1);

    const int ar = wm * 64 + (lane >> 2);
    const int ac = lane & 3;
    const int bn = wn * 32 + (lane >> 2);

    for (int it = 0; it < 8; it++) {
        if (it < 7) asm volatile("cp.async.wait_group 1;" ::: "memory");
        else        asm volatile("cp.async.wait_group 0;" ::: "memory");
        __syncthreads();

        const float*    sA = smem + ((it & 1) ? OFF_A1 : OFF_A0);
        const uint32_t* sB = (const uint32_t*)(smem + ((it & 1) ? OFF_B1 : OFF_B0));

#pragma unroll
        for (int kk = 0; kk < 8; kk++) {
            const int c = kk * 8 + ac;
            uint32_t b[4][2];
#pragma unroll
            for (int nt = 0; nt < 4; nt++) {
                b[nt][0] = sB[(bn + nt * 8) * STRIDE + c];
                b[nt][1] = sB[(bn + nt * 8) * STRIDE + c + 4];
            }
#pragma unroll
            for (int mt = 0; mt < 4; mt++) {
                const int r = ar + mt * 16;
                uint32_t a0 = f2tf32(sA[r * STRIDE + c]);
                uint32_t a1 = f2tf32(sA[(r + 8) * STRIDE + c]);
                uint32_t a2 = f2tf32(sA[r * STRIDE + c + 4]);
                uint32_t a3 = f2tf32(sA[(r + 8) * STRIDE + c + 4]);
#pragma unroll
                for (int nt = 0; nt < 4; nt++)
                    mma_tf32(acc[mt][nt], a0, a1, a2, a3, b[nt][0], b[nt][1]);
            }
        }
        __syncthreads();

        if (it < 6) {
            if (it & 1) ISSUE_STAGE(it + 2, OFF_A1, OFF_B1);
            else        ISSUE_STAGE(it + 2, OFF_A0, OFF_B0);
        }
    }

    // ---- epilogue: + bias, write fp32 Y ----
#pragma unroll
    for (int nt = 0; nt < 4; nt++) {
        const int c  = col0 + wn * 32 + nt * 8 + ((lane & 3) << 1);
        const float b0 = __ldg(bfc + c);
        const float b1 = __ldg(bfc + c + 1);
#pragma unroll
        for (int mt = 0; mt < 4; mt++) {
            const int r = row0 + wm * 64 + mt * 16 + (lane >> 2);
            float2 v0 = make_float2(acc[mt][nt][0] + b0, acc[mt][nt][1] + b1);
            float2 v1 = make_float2(acc[mt][nt][2] + b0, acc[mt][nt][3] + b1);
            *(float2*)&g_Y[(size_t)r * HID + c]       = v0;
            *(float2*)&g_Y[(size_t)(r + 8) * HID + c] = v1;
        }
    }
}

// ---------------------------------------------------------------------------
// Kernel 2: per-batch attention (unchanged — 72.8% DRAM already).
// ---------------------------------------------------------------------------
__global__ __launch_bounds__(256)
void attn_kernel(const float* __restrict__ X, float* __restrict__ out)
{
    const int b    = blockIdx.x;
    const int tid  = threadIdx.x;
    const int lane = tid & 31;
    const int warp = tid >> 5;

    __shared__ float sRed[8][45];
    __shared__ float sAttn[81];
    __shared__ float sB[81];
    __shared__ float sP[81];

    const float* Yb = g_Y + (size_t)b * (HW81 * HID);

    float acc[45];
#pragma unroll
    for (int i = 0; i < 45; i++) acc[i] = 0.f;

#pragma unroll
    for (int p = 0; p < 9; p++) {
        float z[9];
#pragma unroll
        for (int q = 0; q < 9; q++) {
            int rm = (3 * (q / 3) + p / 3) * 9 + 3 * (q % 3) + (p % 3);
            z[q] = Yb[rm * HID + tid];
        }
        int cidx = 0;
#pragma unroll
        for (int n = 0; n < 9; n++)
#pragma unroll
            for (int m = n; m < 9; m++)
                acc[cidx++] += z[n] * z[m];
    }
#pragma unroll
    for (int i = 0; i < 45; i++) {
        float v = acc[i];
#pragma unroll
        for (int o = 16; o > 0; o >>= 1) v += __shfl_xor_sync(0xffffffffu, v, o);
        if (lane == 0) sRed[warp][i] = v;
    }
    __syncthreads();

    if (tid < 45) {
        float s = 0.f;
#pragma unroll
        for (int w = 0; w < 8; w++) s += sRed[w][tid];
        int n = 0, m = tid;
        while (m >= 9 - n) { m -= (9 - n); n++; }
        m += n;
        float v = s * (1.0f / 48.0f);     // (hidden*P)^-0.5 = 1/sqrt(2304)
        if (n == m) v -= 100.0f;
        sAttn[n * 9 + m] = v;
        sAttn[m * 9 + n] = v;
    }
    __syncthreads();

    if (tid < 81) {
        int n = tid / 9, k = tid % 9;
        float s = 0.f;
#pragma unroll
        for (int m = 0; m < 9; m++) s += sAttn[n * 9 + m] * sAttn[k * 9 + m];
        sB[tid] = s * (1.0f / 3.0f);
    }
    __syncthreads();

    if (tid < 9) {
        int n = tid;
        float mx = -1e30f;
#pragma unroll
        for (int k = 0; k < 9; k++) mx = fmaxf(mx, sB[n * 9 + k]);
        float e[9]; float se = 0.f;
#pragma unroll
        for (int k = 0; k < 9; k++) { e[k] = expf(sB[n * 9 + k] - mx); se += e[k]; }
        float inv = 1.0f / se;
        float L[9]; float mx2 = -1e30f;
#pragma unroll
        for (int k = 0; k < 9; k++) {
            L[k] = sAttn[n * 9 + k] + e[k] * inv;
            mx2 = fmaxf(mx2, L[k]);
        }
        float e2[9]; float s2 = 0.f;
#pragma unroll
        for (int k = 0; k < 9; k++) { e2[k] = expf(L[k] - mx2); s2 += e2[k]; }
        float inv2 = 1.0f / s2;
#pragma unroll
        for (int k = 0; k < 9; k++) sP[n * 9 + k] = e2[k] * inv2;
    }
    __syncthreads();

    const float2* Xb = (const float2*)X + (size_t)b * (HW81 * 256);
    float2*       Ob = (float2*)out     + (size_t)b * (HW81 * 256);

#pragma unroll
    for (int p = 0; p < 9; p++) {
        float2 v[9];
#pragma unroll
        for (int m = 0; m < 9; m++) {
            int rm = (3 * (m / 3) + p / 3) * 9 + 3 * (m % 3) + (p % 3);
            v[m] = Xb[rm * 256 + tid];
        }
#pragma unroll
        for (int n = 0; n < 9; n++) {
            int rm = (3 * (n / 3) + p / 3) * 9 + 3 * (n % 3) + (p % 3);
            float2 o = make_float2(0.f, 0.f);
#pragma unroll
            for (int m = 0; m < 9; m++) {
                float w = sP[n * 9 + m];
                o.x += w * v[m].x;
                o.y += w * v[m].y;
            }
            Ob[rm * 256 + tid] = o;
        }
    }
}

// ---------------------------------------------------------------------------
extern "C" void kernel_launch(void* const* d_in, const int* in_sizes, int n_in,
                              void* d_out, int out_size)
{
    const float* x   = (const float*)d_in[0];   // [2048, 9, 9, 512] fp32
    const float* Wf  = (const float*)d_in[1];   // [256, 512] fp32
    const float* bfc = (const float*)d_in[2];   // [256] fp32
    float* out = (float*)d_out;

    cudaFuncSetAttribute(gemm_tf32, cudaFuncAttributeMaxDynamicSharedMemorySize,
                         SMEM_FLOATS * 4);

    wprep_kernel<<<256, 512>>>(Wf);
    dim3 g1(HID / 128, MROWS / 256);            // (2, 648)
    gemm_tf32<<<g1, 512, SMEM_FLOATS * 4>>>(x, bfc);
    attn_kernel<<<BATCH, 256>>>(x, out);
}